// round 1
// baseline (speedup 1.0000x reference)
#include <cuda_runtime.h>

// Sorted segment-sum: pred_rgb[r] = sum_{i in ray r} w[i] * rgb[i]
// N_SAMPLES = 4194304, N_RAYS = 65536, indices sorted ascending.
//
// Strategy: each thread owns ITEMS=16 contiguous samples. All loads are
// 128-bit vectorized (alignment guaranteed: base offsets are multiples of
// 64B / 64B / 192B). Runs of equal ray index are accumulated in registers;
// global atomicAdd only at run boundaries (~1.25 boundaries / 16 samples
// at 64 samples/ray avg), so atomic traffic is ~1M ops over 196K addresses.

#define ITEMS 16
#define TPB 256

__global__ void zero_out_kernel(float* __restrict__ out, int n) {
    int i = blockIdx.x * blockDim.x + threadIdx.x;
    if (i < n) out[i] = 0.0f;
}

__global__ __launch_bounds__(TPB) void seg_sum_kernel(
    const float* __restrict__ rgb,
    const float* __restrict__ w,
    const int*   __restrict__ idx,
    float* __restrict__ out,
    int n)
{
    long long base = (long long)(blockIdx.x * TPB + threadIdx.x) * ITEMS;
    if (base >= n) return;

    const int4*   idx4 = reinterpret_cast<const int4*>(idx + base);
    const float4* w4   = reinterpret_cast<const float4*>(w + base);
    const float4* r4   = reinterpret_cast<const float4*>(rgb + base * 3);

    int   id[ITEMS];
    float wt[ITEMS];
    float rv[ITEMS * 3];

    // Front-batched vectorized loads (MLP: 20 independent LDG.128 in flight)
    #pragma unroll
    for (int g = 0; g < ITEMS / 4; g++) {
        int4 i4 = idx4[g];
        id[g * 4 + 0] = i4.x; id[g * 4 + 1] = i4.y;
        id[g * 4 + 2] = i4.z; id[g * 4 + 3] = i4.w;
        float4 wv = w4[g];
        wt[g * 4 + 0] = wv.x; wt[g * 4 + 1] = wv.y;
        wt[g * 4 + 2] = wv.z; wt[g * 4 + 3] = wv.w;
        float4 a = r4[g * 3 + 0];
        float4 b = r4[g * 3 + 1];
        float4 c = r4[g * 3 + 2];
        rv[g * 12 + 0]  = a.x; rv[g * 12 + 1]  = a.y; rv[g * 12 + 2]  = a.z;
        rv[g * 12 + 3]  = a.w; rv[g * 12 + 4]  = b.x; rv[g * 12 + 5]  = b.y;
        rv[g * 12 + 6]  = b.z; rv[g * 12 + 7]  = b.w; rv[g * 12 + 8]  = c.x;
        rv[g * 12 + 9]  = c.y; rv[g * 12 + 10] = c.z; rv[g * 12 + 11] = c.w;
    }

    // Run-length accumulate; atomics only on segment change.
    int cur = id[0];
    float a0 = 0.f, a1 = 0.f, a2 = 0.f;
    #pragma unroll
    for (int i = 0; i < ITEMS; i++) {
        if (id[i] != cur) {
            atomicAdd(&out[cur * 3 + 0], a0);
            atomicAdd(&out[cur * 3 + 1], a1);
            atomicAdd(&out[cur * 3 + 2], a2);
            cur = id[i];
            a0 = a1 = a2 = 0.f;
        }
        float wi = wt[i];
        a0 = fmaf(wi, rv[i * 3 + 0], a0);
        a1 = fmaf(wi, rv[i * 3 + 1], a1);
        a2 = fmaf(wi, rv[i * 3 + 2], a2);
    }
    atomicAdd(&out[cur * 3 + 0], a0);
    atomicAdd(&out[cur * 3 + 1], a1);
    atomicAdd(&out[cur * 3 + 2], a2);
}

extern "C" void kernel_launch(void* const* d_in, const int* in_sizes, int n_in,
                              void* d_out, int out_size)
{
    const float* rgb = (const float*)d_in[0];
    const float* w   = (const float*)d_in[1];
    const int*   idx = (const int*)d_in[2];
    float* out = (float*)d_out;

    int n = in_sizes[2];  // number of samples (= len(ray_indices))

    // Output is poisoned; zero it first (ordered on the same stream).
    int zb = (out_size + TPB - 1) / TPB;
    zero_out_kernel<<<zb, TPB>>>(out, out_size);

    int total_threads = (n + ITEMS - 1) / ITEMS;
    int blocks = (total_threads + TPB - 1) / TPB;
    seg_sum_kernel<<<blocks, TPB>>>(rgb, w, idx, out, n);
}